// round 2
// baseline (speedup 1.0000x reference)
#include <cuda_runtime.h>

// Problem constants (fixed by reference)
#define Bn      256
#define Tn      24
#define Dn      2
#define Nn      512
#define Hn      128
#define G3n     384     // 3*H
#define NCOL    64      // sensor columns per block
#define PITCH   68      // floats per state row in smem (pad to avoid STS conflicts; 68*4B multiple of 16B)
#define NTHREADS 256

typedef unsigned long long ull;

__device__ __forceinline__ ull pack2(float lo, float hi) {
    ull r;
    asm("mov.b64 %0, {%1, %2};" : "=l"(r) : "f"(lo), "f"(hi));
    return r;
}
__device__ __forceinline__ void unpack2(ull v, float& lo, float& hi) {
    asm("mov.b64 {%0, %1}, %2;" : "=f"(lo), "=f"(hi) : "l"(v));
}
// packed f32x2 FMA: acc = a*b + acc  (2 MACs / instruction, Blackwell)
__device__ __forceinline__ void fma2(ull& acc, ull a, ull b) {
    asm("fma.rn.f32x2 %0, %1, %2, %0;" : "+l"(acc) : "l"(a), "l"(b));
}
__device__ __forceinline__ float sigm(float x) {
    x = fminf(fmaxf(x, -30.f), 30.f);
    float e = __expf(-x);
    return __fdividef(1.f, 1.f + e);
}
__device__ __forceinline__ float tanh_(float x) {
    x = fminf(fmaxf(x, -15.f), 15.f);
    float e = __expf(-2.f * x);
    return __fdividef(1.f - e, 1.f + e);
}
__device__ __forceinline__ float4 ld4(const float* p) {
    return __ldg((const float4*)p);
}

// acc[a][p] += W[k][a] * sh[k][2p..2p+1], k = 0..127.
// W points at (row 0, this thread's 4-gate column group); row stride = 384 floats.
// sh is a state tile base; all lanes of a warp share cb -> LDS broadcasts.
__device__ __forceinline__ void pass_mm(const float* __restrict__ W,
                                        const float* sh, int cb,
                                        ull acc[4][4]) {
    const float* wp = W;
    const float* hp = sh + cb;
    #pragma unroll 4
    for (int k = 0; k < Hn; ++k) {
        float4 w = __ldg((const float4*)wp);
        ulonglong2 ha = *(const ulonglong2*)(hp);       // cols cb..cb+3 (2 packed pairs)
        ulonglong2 hb = *(const ulonglong2*)(hp + 4);   // cols cb+4..cb+7
        ull w0 = pack2(w.x, w.x);
        ull w1 = pack2(w.y, w.y);
        ull w2 = pack2(w.z, w.z);
        ull w3 = pack2(w.w, w.w);
        fma2(acc[0][0], w0, ha.x); fma2(acc[0][1], w0, ha.y);
        fma2(acc[0][2], w0, hb.x); fma2(acc[0][3], w0, hb.y);
        fma2(acc[1][0], w1, ha.x); fma2(acc[1][1], w1, ha.y);
        fma2(acc[1][2], w1, hb.x); fma2(acc[1][3], w1, hb.y);
        fma2(acc[2][0], w2, ha.x); fma2(acc[2][1], w2, ha.y);
        fma2(acc[2][2], w2, hb.x); fma2(acc[2][3], w2, hb.y);
        fma2(acc[3][0], w3, ha.x); fma2(acc[3][1], w3, ha.y);
        fma2(acc[3][2], w3, hb.x); fma2(acc[3][3], w3, hb.y);
        wp += G3n;
        hp += PITCH;
    }
}

__device__ __forceinline__ void acc_to_f(const ull acc[4][4], float f[4][8]) {
    #pragma unroll
    for (int a = 0; a < 4; ++a)
        #pragma unroll
        for (int p = 0; p < 4; ++p)
            unpack2(acc[a][p], f[a][2 * p], f[a][2 * p + 1]);
}

__global__ void __launch_bounds__(NTHREADS, 1)
gru2_kernel(const float* __restrict__ x,
            const float* __restrict__ Wx0, const float* __restrict__ Wh0,
            const float* __restrict__ bx0, const float* __restrict__ bh0,
            const float* __restrict__ Wx1, const float* __restrict__ Wh1,
            const float* __restrict__ bx1, const float* __restrict__ bh1,
            float* __restrict__ out) {
    extern __shared__ float sm[];
    float* sh0 = sm;                      // [128][PITCH]
    float* sh1 = sm + Hn * PITCH;         // [128][PITCH]
    float* sx  = sm + 2 * Hn * PITCH;     // [2][64]

    const int tid  = threadIdx.x;
    const int tj   = tid & 31;            // 32 j-groups (whole warp shares tc -> broadcasts)
    const int tc   = tid >> 5;            // 8 c-groups
    const int jb   = tj * 4;              // this thread's 4 hidden units
    const int cb   = tc * 8;              // this thread's 8 columns

    const int bidx = blockIdx.x >> 3;             // batch
    const int n0   = (blockIdx.x & 7) * NCOL;     // sensor-channel tile base

    // zero initial state (pad too; harmless)
    for (int i = tid; i < 2 * Hn * PITCH; i += NTHREADS) sm[i] = 0.f;

    // biases / Wx0 slices this thread needs (L1-resident, load once)
    float4 t4;
    float bh0r[4], bx0r[4], bh0z[4], bx0z[4], bh0n[4], bx0n[4];
    float w0ar[4], w0br[4], w0az[4], w0bz[4], w0an[4], w0bn[4];
    float b1r[4], b1z[4], b1in[4], b1hn[4];
    t4 = ld4(bh0 + jb);        bh0r[0]=t4.x; bh0r[1]=t4.y; bh0r[2]=t4.z; bh0r[3]=t4.w;
    t4 = ld4(bx0 + jb);        bx0r[0]=t4.x; bx0r[1]=t4.y; bx0r[2]=t4.z; bx0r[3]=t4.w;
    t4 = ld4(bh0 + 128 + jb);  bh0z[0]=t4.x; bh0z[1]=t4.y; bh0z[2]=t4.z; bh0z[3]=t4.w;
    t4 = ld4(bx0 + 128 + jb);  bx0z[0]=t4.x; bx0z[1]=t4.y; bx0z[2]=t4.z; bx0z[3]=t4.w;
    t4 = ld4(bh0 + 256 + jb);  bh0n[0]=t4.x; bh0n[1]=t4.y; bh0n[2]=t4.z; bh0n[3]=t4.w;
    t4 = ld4(bx0 + 256 + jb);  bx0n[0]=t4.x; bx0n[1]=t4.y; bx0n[2]=t4.z; bx0n[3]=t4.w;
    t4 = ld4(Wx0 + jb);              w0ar[0]=t4.x; w0ar[1]=t4.y; w0ar[2]=t4.z; w0ar[3]=t4.w;
    t4 = ld4(Wx0 + G3n + jb);        w0br[0]=t4.x; w0br[1]=t4.y; w0br[2]=t4.z; w0br[3]=t4.w;
    t4 = ld4(Wx0 + 128 + jb);        w0az[0]=t4.x; w0az[1]=t4.y; w0az[2]=t4.z; w0az[3]=t4.w;
    t4 = ld4(Wx0 + G3n + 128 + jb);  w0bz[0]=t4.x; w0bz[1]=t4.y; w0bz[2]=t4.z; w0bz[3]=t4.w;
    t4 = ld4(Wx0 + 256 + jb);        w0an[0]=t4.x; w0an[1]=t4.y; w0an[2]=t4.z; w0an[3]=t4.w;
    t4 = ld4(Wx0 + G3n + 256 + jb);  w0bn[0]=t4.x; w0bn[1]=t4.y; w0bn[2]=t4.z; w0bn[3]=t4.w;
    {
        float4 a, b;
        a = ld4(bx1 + jb);        b = ld4(bh1 + jb);
        b1r[0]=a.x+b.x; b1r[1]=a.y+b.y; b1r[2]=a.z+b.z; b1r[3]=a.w+b.w;
        a = ld4(bx1 + 128 + jb);  b = ld4(bh1 + 128 + jb);
        b1z[0]=a.x+b.x; b1z[1]=a.y+b.y; b1z[2]=a.z+b.z; b1z[3]=a.w+b.w;
        a = ld4(bx1 + 256 + jb);
        b1in[0]=a.x; b1in[1]=a.y; b1in[2]=a.z; b1in[3]=a.w;
        b = ld4(bh1 + 256 + jb);
        b1hn[0]=b.x; b1hn[1]=b.y; b1hn[2]=b.z; b1hn[3]=b.w;
    }

    __syncthreads();

    for (int t = 0; t < Tn; ++t) {
        // ---- stage x_t (2 x 64 floats) ----
        if (tid < Dn * NCOL) {
            int d = tid >> 6, c = tid & 63;
            sx[d * NCOL + c] =
                x[(((size_t)bidx * Tn + t) * Dn + d) * Nn + n0 + c];
        }
        __syncthreads();

        float xa[8], xb[8];
        #pragma unroll
        for (int cc = 0; cc < 8; ++cc) {
            xa[cc] = sx[cb + cc];
            xb[cc] = sx[NCOL + cb + cc];
        }

        // ================= layer 0 =================
        float R[4][8], Nv[4][8], h0n[4][8];
        {   // r gate
            ull acc[4][4] = {};
            pass_mm(Wh0 + jb, sh0, cb, acc);
            float pre[4][8]; acc_to_f(acc, pre);
            #pragma unroll
            for (int a = 0; a < 4; ++a)
                #pragma unroll
                for (int cc = 0; cc < 8; ++cc)
                    R[a][cc] = sigm(pre[a][cc] + bh0r[a] + bx0r[a]
                                    + w0ar[a] * xa[cc] + w0br[a] * xb[cc]);
        }
        {   // n gate
            ull acc[4][4] = {};
            pass_mm(Wh0 + 256 + jb, sh0, cb, acc);
            float hn[4][8]; acc_to_f(acc, hn);
            #pragma unroll
            for (int a = 0; a < 4; ++a)
                #pragma unroll
                for (int cc = 0; cc < 8; ++cc) {
                    float iv = bx0n[a] + w0an[a] * xa[cc] + w0bn[a] * xb[cc];
                    Nv[a][cc] = tanh_(iv + R[a][cc] * (hn[a][cc] + bh0n[a]));
                }
        }
        {   // z gate + update
            ull acc[4][4] = {};
            pass_mm(Wh0 + 128 + jb, sh0, cb, acc);
            float pre[4][8]; acc_to_f(acc, pre);
            #pragma unroll
            for (int a = 0; a < 4; ++a)
                #pragma unroll
                for (int cc = 0; cc < 8; ++cc) {
                    float z = sigm(pre[a][cc] + bh0z[a] + bx0z[a]
                                   + w0az[a] * xa[cc] + w0bz[a] * xb[cc]);
                    float hold = sh0[(jb + a) * PITCH + cb + cc];
                    h0n[a][cc] = (1.f - z) * Nv[a][cc] + z * hold;
                }
        }
        __syncthreads();   // all reads of old sh0 done
        #pragma unroll
        for (int a = 0; a < 4; ++a) {
            *(float4*)(sh0 + (jb + a) * PITCH + cb) =
                make_float4(h0n[a][0], h0n[a][1], h0n[a][2], h0n[a][3]);
            *(float4*)(sh0 + (jb + a) * PITCH + cb + 4) =
                make_float4(h0n[a][4], h0n[a][5], h0n[a][6], h0n[a][7]);
        }
        __syncthreads();   // new sh0 visible

        // ================= layer 1 =================
        float h1n[4][8];
        {   // r gate: K=256 (h0 via Wx1, h1 via Wh1)
            ull acc[4][4] = {};
            pass_mm(Wx1 + jb, sh0, cb, acc);
            pass_mm(Wh1 + jb, sh1, cb, acc);
            float pre[4][8]; acc_to_f(acc, pre);
            #pragma unroll
            for (int a = 0; a < 4; ++a)
                #pragma unroll
                for (int cc = 0; cc < 8; ++cc)
                    R[a][cc] = sigm(pre[a][cc] + b1r[a]);
        }
        {   // n gate: i_n and h_n kept separate
            ull ai[4][4] = {};
            pass_mm(Wx1 + 256 + jb, sh0, cb, ai);
            ull ah[4][4] = {};
            pass_mm(Wh1 + 256 + jb, sh1, cb, ah);
            float fi[4][8], fh[4][8];
            acc_to_f(ai, fi); acc_to_f(ah, fh);
            #pragma unroll
            for (int a = 0; a < 4; ++a)
                #pragma unroll
                for (int cc = 0; cc < 8; ++cc)
                    Nv[a][cc] = tanh_(fi[a][cc] + b1in[a]
                                      + R[a][cc] * (fh[a][cc] + b1hn[a]));
        }
        {   // z gate + update
            ull acc[4][4] = {};
            pass_mm(Wx1 + 128 + jb, sh0, cb, acc);
            pass_mm(Wh1 + 128 + jb, sh1, cb, acc);
            float pre[4][8]; acc_to_f(acc, pre);
            #pragma unroll
            for (int a = 0; a < 4; ++a)
                #pragma unroll
                for (int cc = 0; cc < 8; ++cc) {
                    float z = sigm(pre[a][cc] + b1z[a]);
                    float hold = sh1[(jb + a) * PITCH + cb + cc];
                    h1n[a][cc] = (1.f - z) * Nv[a][cc] + z * hold;
                }
        }
        __syncthreads();   // all reads of old sh1 done
        #pragma unroll
        for (int a = 0; a < 4; ++a) {
            *(float4*)(sh1 + (jb + a) * PITCH + cb) =
                make_float4(h1n[a][0], h1n[a][1], h1n[a][2], h1n[a][3]);
            *(float4*)(sh1 + (jb + a) * PITCH + cb + 4) =
                make_float4(h1n[a][4], h1n[a][5], h1n[a][6], h1n[a][7]);
        }
        __syncthreads();   // new sh1 visible (also fences sx for next t)
    }

    // ---- write final hidden states: out[2][B][H][N] ----
    #pragma unroll
    for (int a = 0; a < 4; ++a) {
        const int j = jb + a;
        size_t o0 = ((size_t)bidx * Hn + j) * Nn + n0 + cb;
        size_t o1 = ((size_t)(Bn + bidx) * Hn + j) * Nn + n0 + cb;
        *(float4*)(out + o0)     = *(const float4*)(sh0 + j * PITCH + cb);
        *(float4*)(out + o0 + 4) = *(const float4*)(sh0 + j * PITCH + cb + 4);
        *(float4*)(out + o1)     = *(const float4*)(sh1 + j * PITCH + cb);
        *(float4*)(out + o1 + 4) = *(const float4*)(sh1 + j * PITCH + cb + 4);
    }
}

extern "C" void kernel_launch(void* const* d_in, const int* in_sizes, int n_in,
                              void* d_out, int out_size) {
    const float* x   = (const float*)d_in[0];
    const float* Wx0 = (const float*)d_in[1];
    const float* Wh0 = (const float*)d_in[2];
    const float* bx0 = (const float*)d_in[3];
    const float* bh0 = (const float*)d_in[4];
    const float* Wx1 = (const float*)d_in[5];
    const float* Wh1 = (const float*)d_in[6];
    const float* bx1 = (const float*)d_in[7];
    const float* bh1 = (const float*)d_in[8];
    float* out = (float*)d_out;

    const size_t smem = (size_t)(2 * Hn * PITCH + Dn * NCOL) * sizeof(float);
    cudaFuncSetAttribute(gru2_kernel,
                         cudaFuncAttributeMaxDynamicSharedMemorySize, (int)smem);

    dim3 grid(Bn * (Nn / NCOL));   // 2048 blocks
    gru2_kernel<<<grid, NTHREADS, smem>>>(x, Wx0, Wh0, bx0, bh0,
                                          Wx1, Wh1, bx1, bh1, out);
}